// round 12
// baseline (speedup 1.0000x reference)
#include <cuda_runtime.h>
#include <cuda_bf16.h>
#include <cstdint>

#define THITA 0.0001f
#define NPOS 2304
#define SP 68
#define WP 65
#define EXP_SHIFT 16.0f

// Scratch (device globals)
__device__ __align__(128) __nv_bfloat16 g_qb[4 * 2304 * 64];
__device__ __align__(128) __nv_bfloat16 g_kb[4 * 2304 * 64];
__device__ __align__(128) __nv_bfloat16 g_vb[4 * 64 * 2304];
__device__ __align__(128) float         g_x1[4 * 64 * 2304];
__device__ __align__(128) float         g_part[288 * 4096];
__device__ __align__(128) float         g_lpart[288 * 64];
__device__ int g_flag[144];

// ===========================================================================
// Generic-PTX helpers
// ===========================================================================
__device__ __forceinline__ uint32_t smem_u32(const void* p) {
    uint32_t a;
    asm("{ .reg .u64 t; cvta.to.shared.u64 t, %1; cvt.u32.u64 %0, t; }" : "=r"(a) : "l"(p));
    return a;
}

#define CP16(dst, src) asm volatile("cp.async.cg.shared.global [%0], [%1], 16;" :: "r"(dst), "l"(src))
#define CP_COMMIT()    asm volatile("cp.async.commit_group;" ::: "memory")
#define CP_WAIT1()     asm volatile("cp.async.wait_group 1;" ::: "memory")
#define CP_WAIT2()     asm volatile("cp.async.wait_group 2;" ::: "memory")

__device__ __forceinline__ void ldsm4(uint32_t* r, uint32_t addr) {
    asm volatile("ldmatrix.sync.aligned.m8n8.x4.shared.b16 {%0,%1,%2,%3}, [%4];"
                 : "=r"(r[0]), "=r"(r[1]), "=r"(r[2]), "=r"(r[3]) : "r"(addr));
}

__device__ __forceinline__ void mma16816(float* c, const uint32_t* a,
                                         uint32_t b0, uint32_t b1) {
    asm volatile("mma.sync.aligned.m16n8k16.row.col.f32.bf16.bf16.f32 "
                 "{%0,%1,%2,%3}, {%4,%5,%6,%7}, {%8,%9}, {%0,%1,%2,%3};"
                 : "+f"(c[0]), "+f"(c[1]), "+f"(c[2]), "+f"(c[3])
                 : "r"(a[0]), "r"(a[1]), "r"(a[2]), "r"(a[3]), "r"(b0), "r"(b1));
}

__device__ __forceinline__ uint32_t pack_bf16x2(float lo, float hi) {
    uint32_t r;
    asm("cvt.rn.bf16x2.f32 %0, %1, %2;" : "=r"(r) : "f"(hi), "f"(lo));
    return r;
}

// ===========================================================================
// fp32 64x64 GEMM (x1 only)
// ===========================================================================
__device__ __forceinline__ void gemm64_relu(
    const float* __restrict__ In, const float* __restrict__ Wt,
    const float* __restrict__ bias, float* __restrict__ Out, int tx, int ty)
{
    float acc[4][4];
#pragma unroll
    for (int i = 0; i < 4; i++)
#pragma unroll
        for (int j = 0; j < 4; j++) acc[i][j] = 0.f;
#pragma unroll 16
    for (int c = 0; c < 64; ++c) {
        float4 xv = *reinterpret_cast<const float4*>(In + c * SP + tx * 4);
        float w0 = Wt[c * WP + ty * 4 + 0];
        float w1 = Wt[c * WP + ty * 4 + 1];
        float w2 = Wt[c * WP + ty * 4 + 2];
        float w3 = Wt[c * WP + ty * 4 + 3];
        acc[0][0] += w0 * xv.x; acc[0][1] += w0 * xv.y; acc[0][2] += w0 * xv.z; acc[0][3] += w0 * xv.w;
        acc[1][0] += w1 * xv.x; acc[1][1] += w1 * xv.y; acc[1][2] += w1 * xv.z; acc[1][3] += w1 * xv.w;
        acc[2][0] += w2 * xv.x; acc[2][1] += w2 * xv.y; acc[2][2] += w2 * xv.z; acc[2][3] += w2 * xv.w;
        acc[3][0] += w3 * xv.x; acc[3][1] += w3 * xv.y; acc[3][2] += w3 * xv.z; acc[3][3] += w3 * xv.w;
    }
#pragma unroll
    for (int i = 0; i < 4; i++) {
        float bb = bias[ty * 4 + i];
        float4 o4;
        o4.x = fmaxf(acc[i][0] + bb, 0.f);
        o4.y = fmaxf(acc[i][1] + bb, 0.f);
        o4.z = fmaxf(acc[i][2] + bb, 0.f);
        o4.w = fmaxf(acc[i][3] + bb, 0.f);
        *reinterpret_cast<float4*>(Out + (ty * 4 + i) * SP + tx * 4) = o4;
    }
}

__device__ __forceinline__ void loadWt(const float* __restrict__ Wg,
                                       float* __restrict__ Wt, int tid)
{
#pragma unroll
    for (int idx = tid; idx < 4096; idx += 256) {
        int o = idx >> 6, c = idx & 63;
        Wt[c * WP + o] = Wg[idx];
    }
}

__device__ __forceinline__ void convW(const float* __restrict__ Wg,
                                      char* smc, uint32_t woff, int tid)
{
#pragma unroll
    for (int idx = tid; idx < 4096; idx += 256) {
        int o = idx >> 6, c = idx & 63;
        *(__nv_bfloat16*)(smc + woff + o * 144 + c * 2) = __float2bfloat16(Wg[idx]);
    }
}

// ===========================================================================
// bf16 tensor-core 64x64 GEMM + bias + relu
// ===========================================================================
__device__ __forceinline__ void gemm_tc(uint32_t sb, char* smc,
    uint32_t aoff, uint32_t woff, const float* __restrict__ biasS, uint32_t ooff,
    int lane, int w4, int h)
{
    const int bro = ((lane & 16) >> 1) + (lane & 7);
    const int bco = (lane & 8) * 2;
    uint32_t af[4][4];
    uint32_t abase = sb + aoff + (w4 * 16 + (lane & 15)) * 144 + ((lane >> 4) << 4);
#pragma unroll
    for (int ks = 0; ks < 4; ++ks) ldsm4(af[ks], abase + ks * 32);

    float C[4][4];
#pragma unroll
    for (int j = 0; j < 4; ++j)
#pragma unroll
        for (int e = 0; e < 4; ++e) C[j][e] = 0.f;

#pragma unroll
    for (int ks = 0; ks < 4; ++ks) {
#pragma unroll
        for (int p = 0; p < 2; ++p) {
            uint32_t wb[4];
            ldsm4(wb, sb + woff + (h * 32 + 16 * p + bro) * 144 + ks * 32 + bco);
            mma16816(C[2 * p],     af[ks], wb[0], wb[1]);
            mma16816(C[2 * p + 1], af[ks], wb[2], wb[3]);
        }
    }

    const int rl = w4 * 16 + (lane >> 2), rh = rl + 8;
#pragma unroll
    for (int j = 0; j < 4; ++j) {
        int n = h * 32 + 8 * j + (lane & 3) * 2;
        float b0 = biasS[n], b1 = biasS[n + 1];
        uint32_t u0 = pack_bf16x2(fmaxf(C[j][0] + b0, 0.f), fmaxf(C[j][1] + b1, 0.f));
        uint32_t u1 = pack_bf16x2(fmaxf(C[j][2] + b0, 0.f), fmaxf(C[j][3] + b1, 0.f));
        *(uint32_t*)(smc + ooff + rl * 144 + n * 2) = u0;
        *(uint32_t*)(smc + ooff + rh * 144 + n * 2) = u1;
    }
}

// ===========================================================================
// Merged projection kernel (unchanged from R11)
// ===========================================================================
#define AOFF  0
#define BOFF  9216
#define S1OFF 17408
#define WTOFF 34816
#define W0OFF 51456
#define W1OFF 60672
#define W2OFF 69888
#define BS0   79104
#define BS1   79360
#define BS2   79616
#define P2_SMEM 79872

__global__ __launch_bounds__(256, 2)
void proj2_kernel(const float* __restrict__ x, const float* __restrict__ event,
                  const float* __restrict__ Wx0, const float* __restrict__ bx0,
                  const float* __restrict__ Wx1, const float* __restrict__ bx1,
                  const float* __restrict__ We0, const float* __restrict__ be0,
                  const float* __restrict__ We1, const float* __restrict__ be1,
                  const float* __restrict__ Wq,  const float* __restrict__ bq,
                  const float* __restrict__ Wk,  const float* __restrict__ bk,
                  const float* __restrict__ Wv,  const float* __restrict__ bv)
{
    extern __shared__ char smc[];
    const uint32_t sb = smem_u32(smc);
    const int tid = threadIdx.x;
    const int lane = tid & 31, w = tid >> 5;
    const int w4 = w & 3, h = w >> 2;
    const int path = blockIdx.x / 144;
    const int id   = blockIdx.x % 144;
    const int b = id / 36, n0 = (id % 36) * 64;

    float* bias0 = (float*)(smc + BS0);
    float* bias1 = (float*)(smc + BS1);
    float* bias2 = (float*)(smc + BS2);
    if (tid < 64) {
        bias0[tid] = path == 0 ? bx1[tid] : be0[tid];
        bias1[tid] = path == 0 ? bq[tid]  : be1[tid];
        bias2[tid] = path == 0 ? bv[tid]  : bk[tid];
    }
    if (path == 0 && tid == 0) g_flag[id] = 0;

    if (path == 0) {
        float* S0 = (float*)smc;
        float* S1 = (float*)(smc + S1OFF);
        float* Wt = (float*)(smc + WTOFF);
        const float* xb = x + b * 64 * NPOS + n0;
#pragma unroll
        for (int idx = tid; idx < 4096; idx += 256) {
            int c = idx >> 6, j = idx & 63;
            S0[c * SP + j] = xb[c * NPOS + j];
        }
        loadWt(Wx0, Wt, tid);
        convW(Wx1, smc, W0OFF, tid);
        convW(Wq,  smc, W1OFF, tid);
        convW(Wv,  smc, W2OFF, tid);
        __syncthreads();
        gemm64_relu(S0, Wt, bx0, S1, tid & 15, tid >> 4);
        __syncthreads();

        float* x1g = g_x1 + b * 64 * NPOS + n0;
#pragma unroll
        for (int idx = tid; idx < 4096; idx += 256) {
            int c = idx >> 6, j = idx & 63;
            x1g[c * NPOS + j] = S1[c * SP + j];
        }
#pragma unroll
        for (int idx = tid; idx < 4096; idx += 256) {
            int j = idx & 63, o = idx >> 6;
            *(__nv_bfloat16*)(smc + AOFF + j * 144 + o * 2) = __float2bfloat16(S1[o * SP + j]);
        }
        __syncthreads();

        gemm_tc(sb, smc, AOFF, W0OFF, bias0, BOFF, lane, w4, h);   // x2 -> B
        __syncthreads();
        gemm_tc(sb, smc, BOFF, W1OFF, bias1, AOFF, lane, w4, h);   // q -> A
        __syncthreads();
        {
            char* qg = (char*)(g_qb + (size_t)(b * NPOS + n0) * 64);
#pragma unroll
            for (int it = 0; it < 2; ++it) {
                int idx = tid + it * 256;
                int p = idx >> 3, c16 = (idx & 7) * 16;
                *(uint4*)(qg + p * 128 + c16) = *(const uint4*)(smc + AOFF + p * 144 + c16);
            }
        }
        __syncthreads();
        gemm_tc(sb, smc, BOFF, W2OFF, bias2, AOFF, lane, w4, h);   // v -> A
        __syncthreads();
        {
            char* vbg = (char*)(g_vb + (size_t)b * 64 * NPOS + n0);
#pragma unroll
            for (int idx = tid; idx < 2048; idx += 256) {
                int c = idx >> 5, p2 = (idx & 31) * 2;
                uint32_t lo = *(const uint16_t*)(smc + AOFF + p2 * 144 + c * 2);
                uint32_t hi = *(const uint16_t*)(smc + AOFF + (p2 + 1) * 144 + c * 2);
                *(uint32_t*)(vbg + (size_t)c * (NPOS * 2) + p2 * 2) = lo | (hi << 16);
            }
        }
    } else {
        const float* eb = event + (long)b * 64 * 768 * 768;
#pragma unroll
        for (int idx = tid; idx < 4096; idx += 256) {
            int j = idx & 63, c = idx >> 6;
            int n = n0 + j;
            int hh = n / 48;
            int ww = n - hh * 48;
            float v = eb[((long)c * 768 + hh * 16) * 768 + ww * 16];
            *(__nv_bfloat16*)(smc + AOFF + j * 144 + c * 2) = __float2bfloat16(v);
        }
        convW(We0, smc, W0OFF, tid);
        convW(We1, smc, W1OFF, tid);
        convW(Wk,  smc, W2OFF, tid);
        __syncthreads();
        gemm_tc(sb, smc, AOFF, W0OFF, bias0, BOFF, lane, w4, h);   // ef0 -> B
        __syncthreads();
        gemm_tc(sb, smc, BOFF, W1OFF, bias1, AOFF, lane, w4, h);   // ef1 -> A
        __syncthreads();
        gemm_tc(sb, smc, AOFF, W2OFF, bias2, BOFF, lane, w4, h);   // k -> B
        __syncthreads();
        {
            char* kgd = (char*)(g_kb + (size_t)(b * NPOS + n0) * 64);
#pragma unroll
            for (int it = 0; it < 2; ++it) {
                int idx = tid + it * 256;
                int p = idx >> 3, c16 = (idx & 7) * 16;
                *(uint4*)(kgd + p * 128 + c16) = *(const uint4*)(smc + BOFF + p * 144 + c16);
            }
        }
    }
}

// ===========================================================================
// mma.sync attention, software-pipelined S: iteration i interleaves
// O += P(i)·V(i) with S(i+1) = Q·K(i+1). 4 smem stages, loads 3 ahead.
// Fused split-K combine at tail (unchanged).
// ===========================================================================
#define TSTRIDE 144
#define SM_Q   0
#define SM_K   9216                 // 4 stages of 9216 -> ends 46080
#define SM_V   46080                // 4 stages of 9216 -> ends 82944
#define SM_O   9216                 // fp32 64x68 epilogue aliases K stages
#define SM_L   26624
#define ATTN_SMEM 82944
#define KITERS 18

__global__ __launch_bounds__(256, 2)
void attn_mma_kernel(const float* __restrict__ gamma, float* __restrict__ out)
{
    extern __shared__ char smc[];
    const uint32_t sb = smem_u32(smc);
    const int tid = threadIdx.x;
    const int lane = tid & 31, w = tid >> 5;
    const int w4 = w & 3, h = w >> 2;
    const int pairid = blockIdx.x >> 1;
    const int b   = blockIdx.x / 72;
    const int rem = blockIdx.x % 72;
    const int m0  = (rem >> 1) * 64;
    const int kh  = rem & 1;
    const int nbase = kh * 1152;

    const char* qg = (const char*)(g_qb + (size_t)(b * NPOS + m0) * 64);
    const char* kg = (const char*)(g_kb + (size_t)(b * NPOS + nbase) * 64);
    const char* vg = (const char*)(g_vb + (size_t)b * 64 * NPOS) + nbase * 2;

    const int row0 = tid >> 3,         c16_0 = (tid & 7) * 16;
    const int row1 = (tid + 256) >> 3, c16_1 = (tid & 7) * 16;

    // ---- prologue: g0 = Q+K0+V0, g1 = K1+V1, g2 = K2+V2 ----
    CP16(sb + SM_Q + row0 * TSTRIDE + c16_0, qg + row0 * 128 + c16_0);
    CP16(sb + SM_Q + row1 * TSTRIDE + c16_1, qg + row1 * 128 + c16_1);
    CP16(sb + SM_K + row0 * TSTRIDE + c16_0, kg + row0 * 128 + c16_0);
    CP16(sb + SM_K + row1 * TSTRIDE + c16_1, kg + row1 * 128 + c16_1);
    CP16(sb + SM_V + row0 * TSTRIDE + c16_0, vg + (size_t)row0 * (NPOS * 2) + c16_0);
    CP16(sb + SM_V + row1 * TSTRIDE + c16_1, vg + (size_t)row1 * (NPOS * 2) + c16_1);
    CP_COMMIT();
#pragma unroll
    for (int s = 1; s <= 2; ++s) {
        const char* kgs = kg + (size_t)(s * 64) * 128;
        CP16(sb + SM_K + s * 9216 + row0 * TSTRIDE + c16_0, kgs + row0 * 128 + c16_0);
        CP16(sb + SM_K + s * 9216 + row1 * TSTRIDE + c16_1, kgs + row1 * 128 + c16_1);
        CP16(sb + SM_V + s * 9216 + row0 * TSTRIDE + c16_0, vg + (size_t)row0 * (NPOS * 2) + s * 128 + c16_0);
        CP16(sb + SM_V + s * 9216 + row1 * TSTRIDE + c16_1, vg + (size_t)row1 * (NPOS * 2) + s * 128 + c16_1);
        CP_COMMIT();
    }
    CP_WAIT2();          // g0 done (Q, K0, V0); g1,g2 in flight
    __syncthreads();

    uint32_t qf[4][4];
    {
        uint32_t base = sb + SM_Q + (w4 * 16 + (lane & 15)) * TSTRIDE + ((lane >> 4) << 4);
#pragma unroll
        for (int ks = 0; ks < 4; ++ks) ldsm4(qf[ks], base + ks * 32);
    }

    const int bro = ((lane & 16) >> 1) + (lane & 7);
    const int bco = (lane & 8) * 2;

    // S(0) = Q K(0)
    float S[4][4];
#pragma unroll
    for (int j = 0; j < 4; ++j)
#pragma unroll
        for (int e = 0; e < 4; ++e) S[j][e] = 0.f;
#pragma unroll
    for (int ks = 0; ks < 4; ++ks) {
#pragma unroll
        for (int p = 0; p < 2; ++p) {
            uint32_t kb[4];
            ldsm4(kb, sb + SM_K + (h * 32 + 16 * p + bro) * TSTRIDE + ks * 32 + bco);
            mma16816(S[2 * p],     qf[ks], kb[0], kb[1]);
            mma16816(S[2 * p + 1], qf[ks], kb[2], kb[3]);
        }
    }
    CP_WAIT1();          // g1 done (K1,V1); g2 in flight
    __syncthreads();

    float O[8][4];
#pragma unroll
    for (int j = 0; j < 8; ++j)
#pragma unroll
        for (int e = 0; e < 4; ++e) O[j][e] = 0.f;
    float lsum0 = 0.f, lsum1 = 0.f;

    for (int i = 0; i < KITERS; ++i) {
        // issue loads for block i+3 (empty commit keeps group counts uniform)
        if (i + 3 < KITERS) {
            const int n3 = (i + 3) * 64;
            const char* kgs = kg + (size_t)n3 * 128;
            const uint32_t ko = sb + SM_K + ((i + 3) & 3) * 9216;
            const uint32_t vo = sb + SM_V + ((i + 3) & 3) * 9216;
            CP16(ko + row0 * TSTRIDE + c16_0, kgs + row0 * 128 + c16_0);
            CP16(ko + row1 * TSTRIDE + c16_1, kgs + row1 * 128 + c16_1);
            CP16(vo + row0 * TSTRIDE + c16_0, vg + (size_t)row0 * (NPOS * 2) + n3 * 2 + c16_0);
            CP16(vo + row1 * TSTRIDE + c16_1, vg + (size_t)row1 * (NPOS * 2) + n3 * 2 + c16_1);
        }
        CP_COMMIT();

        // P = exp(S - 16) (S computed during previous iteration's mma phase)
        uint32_t P[2][4];
#pragma unroll
        for (int j = 0; j < 4; ++j) {
            float e0 = __expf(S[j][0] - EXP_SHIFT);
            float e1 = __expf(S[j][1] - EXP_SHIFT);
            float e2 = __expf(S[j][2] - EXP_SHIFT);
            float e3 = __expf(S[j][3] - EXP_SHIFT);
            lsum0 += e0 + e1;
            lsum1 += e2 + e3;
            P[j >> 1][(j & 1) * 2 + 0] = pack_bf16x2(e0, e1);
            P[j >> 1][(j & 1) * 2 + 1] = pack_bf16x2(e2, e3);
        }

        // interleaved mma: O += P(i) V(i)  ||  Sn = Q K(i+1)
        const uint32_t vbase = sb + SM_V + (i & 3) * 9216;
        const uint32_t kbase = sb + SM_K + ((i + 1) & 3) * 9216;
        const bool hasNext = (i + 1 < KITERS);

        float Sn[4][4];
#pragma unroll
        for (int j = 0; j < 4; ++j)
#pragma unroll
            for (int e = 0; e < 4; ++e) Sn[j][e] = 0.f;

#pragma unroll
        for (int u = 0; u < 8; ++u) {
            const int step = u & 1, p = u >> 1;
            uint32_t vb[4];
            ldsm4(vb, vbase + (16 * p + bro) * TSTRIDE + h * 64 + step * 32 + bco);
            mma16816(O[2 * p],     P[step], vb[0], vb[1]);
            mma16816(O[2 * p + 1], P[step], vb[2], vb[3]);
            if (hasNext) {
                const int ks = u >> 1, p2 = u & 1;
                uint32_t kb[4];
                ldsm4(kb, kbase + (h * 32 + 16 * p2 + bro) * TSTRIDE + ks * 32 + bco);
                mma16816(Sn[2 * p2],     qf[ks], kb[0], kb[1]);
                mma16816(Sn[2 * p2 + 1], qf[ks], kb[2], kb[3]);
            }
        }
#pragma unroll
        for (int j = 0; j < 4; ++j)
#pragma unroll
            for (int e = 0; e < 4; ++e) S[j][e] = Sn[j][e];

        // wait block i+2 (for next iteration's K(i+2)); block i+3 stays in flight
        CP_WAIT1();
        __syncthreads();
    }

    lsum0 += __shfl_xor_sync(0xffffffffu, lsum0, 1);
    lsum0 += __shfl_xor_sync(0xffffffffu, lsum0, 2);
    lsum1 += __shfl_xor_sync(0xffffffffu, lsum1, 1);
    lsum1 += __shfl_xor_sync(0xffffffffu, lsum1, 2);

    // combine intra-CTA key-half partials in smem
    float* so  = (float*)(smc + SM_O);
    float* lar = (float*)(smc + SM_L);
    const int g = lane >> 2, t2 = (lane & 3) * 2;
    const int m_lo = w4 * 16 + g, m_hi = m_lo + 8;

    if (h == 0) {
#pragma unroll
        for (int j = 0; j < 8; ++j) {
            int c = 8 * j + t2;
            so[c * 68 + m_lo]       = O[j][0];
            so[(c + 1) * 68 + m_lo] = O[j][1];
            so[c * 68 + m_hi]       = O[j][2];
            so[(c + 1) * 68 + m_hi] = O[j][3];
        }
        if ((lane & 3) == 0) { lar[m_lo] = lsum0; lar[m_hi] = lsum1; }
    }
    __syncthreads();
    if (h == 1) {
#pragma unroll
        for (int j = 0; j < 8; ++j) {
            int c = 8 * j + t2;
            so[c * 68 + m_lo]       += O[j][0];
            so[(c + 1) * 68 + m_lo] += O[j][1];
            so[c * 68 + m_hi]       += O[j][2];
            so[(c + 1) * 68 + m_hi] += O[j][3];
        }
        if ((lane & 3) == 0) { lar[m_lo] += lsum0; lar[m_hi] += lsum1; }
    }
    __syncthreads();

    // publish raw partials
    float* pb = g_part + (size_t)blockIdx.x * 4096;
#pragma unroll
    for (int it = 0; it < 4; ++it) {
        int idx = tid + it * 256;
        int c = idx >> 4, m4 = (idx & 15) * 4;
        *(float4*)(pb + c * 64 + m4) = *(const float4*)(so + c * 68 + m4);
    }
    if (tid < 64) g_lpart[blockIdx.x * 64 + tid] = lar[tid];

    __threadfence();
    __shared__ int isLast;
    if (tid == 0) isLast = (atomicAdd(&g_flag[pairid], 1) == 1);
    __syncthreads();
    if (!isLast) return;

    const int peer = blockIdx.x ^ 1;
    const float gm = THITA * gamma[0];
    if (tid < 64) lar[tid] = gm / (lar[tid] + g_lpart[peer * 64 + tid]);
    __syncthreads();

    const float* pp  = g_part + (size_t)peer * 4096;
    const float* x1b = g_x1 + (size_t)b * 64 * NPOS + m0;
    float* ob = out + (size_t)b * 64 * NPOS + m0;
#pragma unroll
    for (int it = 0; it < 4; ++it) {
        int idx = tid + it * 256;
        int c = idx >> 4, m4 = (idx & 15) * 4;
        float4 a4 = *(const float4*)(so + c * 68 + m4);
        float4 b4 = *(const float4*)(pp + c * 64 + m4);
        float4 l4 = *(const float4*)(lar + m4);
        float4 xv = *(const float4*)(x1b + (size_t)c * NPOS + m4);
        float4 r;
        r.x = (a4.x + b4.x) * l4.x + xv.x;
        r.y = (a4.y + b4.y) * l4.y + xv.y;
        r.z = (a4.z + b4.z) * l4.z + xv.z;
        r.w = (a4.w + b4.w) * l4.w + xv.w;
        *(float4*)(ob + (size_t)c * NPOS + m4) = r;
    }
}

// ===========================================================================
extern "C" void kernel_launch(void* const* d_in, const int* in_sizes, int n_in,
                              void* d_out, int out_size)
{
    const float* x     = (const float*)d_in[0];
    const float* event = (const float*)d_in[1];
    const float* Wx0 = (const float*)d_in[2];
    const float* bx0 = (const float*)d_in[3];
    const float* Wx1 = (const float*)d_in[4];
    const float* bx1 = (const float*)d_in[5];
    const float* We0 = (const float*)d_in[6];
    const float* be0 = (const float*)d_in[7];
    const float* We1 = (const float*)d_in[8];
    const float* be1 = (const float*)d_in[9];
    const float* Wq  = (const float*)d_in[10];
    const float* bq  = (const float*)d_in[11];
    const float* Wk  = (const float*)d_in[12];
    const float* bk  = (const float*)d_in[13];
    const float* Wv  = (const float*)d_in[14];
    const float* bv  = (const float*)d_in[15];
    const float* gamma = (const float*)d_in[16];
    float* out = (float*)d_out;

    cudaFuncSetAttribute(proj2_kernel, cudaFuncAttributeMaxDynamicSharedMemorySize, P2_SMEM);
    cudaFuncSetAttribute(attn_mma_kernel, cudaFuncAttributeMaxDynamicSharedMemorySize, ATTN_SMEM);

    proj2_kernel<<<288, 256, P2_SMEM>>>(x, event,
                                        Wx0, bx0, Wx1, bx1,
                                        We0, be0, We1, be1,
                                        Wq, bq, Wk, bk, Wv, bv);
    attn_mma_kernel<<<288, 256, ATTN_SMEM>>>(gamma, out);
}

// round 13
// speedup vs baseline: 1.0561x; 1.0561x over previous
#include <cuda_runtime.h>
#include <cuda_bf16.h>
#include <cstdint>

#define THITA 0.0001f
#define NPOS 2304
#define SP 68
#define WP 65
#define EXP_SHIFT 16.0f

// Scratch (device globals)
__device__ __align__(128) __nv_bfloat16 g_qb[4 * 2304 * 64];
__device__ __align__(128) __nv_bfloat16 g_kb[4 * 2304 * 64];
__device__ __align__(128) __nv_bfloat16 g_vb[4 * 64 * 2304];
__device__ __align__(128) float         g_x1[4 * 64 * 2304];
__device__ __align__(128) float         g_part[288 * 4096];
__device__ __align__(128) float         g_lpart[288 * 64];
__device__ int g_flag[144];

// ===========================================================================
// Generic-PTX helpers
// ===========================================================================
__device__ __forceinline__ uint32_t smem_u32(const void* p) {
    uint32_t a;
    asm("{ .reg .u64 t; cvta.to.shared.u64 t, %1; cvt.u32.u64 %0, t; }" : "=r"(a) : "l"(p));
    return a;
}

#define CP16(dst, src) asm volatile("cp.async.cg.shared.global [%0], [%1], 16;" :: "r"(dst), "l"(src))
#define CP_COMMIT()    asm volatile("cp.async.commit_group;" ::: "memory")
#define CP_WAIT1()     asm volatile("cp.async.wait_group 1;" ::: "memory")

__device__ __forceinline__ void ldsm4(uint32_t* r, uint32_t addr) {
    asm volatile("ldmatrix.sync.aligned.m8n8.x4.shared.b16 {%0,%1,%2,%3}, [%4];"
                 : "=r"(r[0]), "=r"(r[1]), "=r"(r[2]), "=r"(r[3]) : "r"(addr));
}

__device__ __forceinline__ void mma16816(float* c, const uint32_t* a,
                                         uint32_t b0, uint32_t b1) {
    asm volatile("mma.sync.aligned.m16n8k16.row.col.f32.bf16.bf16.f32 "
                 "{%0,%1,%2,%3}, {%4,%5,%6,%7}, {%8,%9}, {%0,%1,%2,%3};"
                 : "+f"(c[0]), "+f"(c[1]), "+f"(c[2]), "+f"(c[3])
                 : "r"(a[0]), "r"(a[1]), "r"(a[2]), "r"(a[3]), "r"(b0), "r"(b1));
}

__device__ __forceinline__ uint32_t pack_bf16x2(float lo, float hi) {
    uint32_t r;
    asm("cvt.rn.bf16x2.f32 %0, %1, %2;" : "=r"(r) : "f"(hi), "f"(lo));
    return r;
}

// ===========================================================================
// fp32 64x64 GEMM (x1 only)
// ===========================================================================
__device__ __forceinline__ void gemm64_relu(
    const float* __restrict__ In, const float* __restrict__ Wt,
    const float* __restrict__ bias, float* __restrict__ Out, int tx, int ty)
{
    float acc[4][4];
#pragma unroll
    for (int i = 0; i < 4; i++)
#pragma unroll
        for (int j = 0; j < 4; j++) acc[i][j] = 0.f;
#pragma unroll 16
    for (int c = 0; c < 64; ++c) {
        float4 xv = *reinterpret_cast<const float4*>(In + c * SP + tx * 4);
        float w0 = Wt[c * WP + ty * 4 + 0];
        float w1 = Wt[c * WP + ty * 4 + 1];
        float w2 = Wt[c * WP + ty * 4 + 2];
        float w3 = Wt[c * WP + ty * 4 + 3];
        acc[0][0] += w0 * xv.x; acc[0][1] += w0 * xv.y; acc[0][2] += w0 * xv.z; acc[0][3] += w0 * xv.w;
        acc[1][0] += w1 * xv.x; acc[1][1] += w1 * xv.y; acc[1][2] += w1 * xv.z; acc[1][3] += w1 * xv.w;
        acc[2][0] += w2 * xv.x; acc[2][1] += w2 * xv.y; acc[2][2] += w2 * xv.z; acc[2][3] += w2 * xv.w;
        acc[3][0] += w3 * xv.x; acc[3][1] += w3 * xv.y; acc[3][2] += w3 * xv.z; acc[3][3] += w3 * xv.w;
    }
#pragma unroll
    for (int i = 0; i < 4; i++) {
        float bb = bias[ty * 4 + i];
        float4 o4;
        o4.x = fmaxf(acc[i][0] + bb, 0.f);
        o4.y = fmaxf(acc[i][1] + bb, 0.f);
        o4.z = fmaxf(acc[i][2] + bb, 0.f);
        o4.w = fmaxf(acc[i][3] + bb, 0.f);
        *reinterpret_cast<float4*>(Out + (ty * 4 + i) * SP + tx * 4) = o4;
    }
}

__device__ __forceinline__ void loadWt(const float* __restrict__ Wg,
                                       float* __restrict__ Wt, int tid)
{
#pragma unroll
    for (int idx = tid; idx < 4096; idx += 256) {
        int o = idx >> 6, c = idx & 63;
        Wt[c * WP + o] = Wg[idx];
    }
}

__device__ __forceinline__ void convW(const float* __restrict__ Wg,
                                      char* smc, uint32_t woff, int tid)
{
#pragma unroll
    for (int idx = tid; idx < 4096; idx += 256) {
        int o = idx >> 6, c = idx & 63;
        *(__nv_bfloat16*)(smc + woff + o * 144 + c * 2) = __float2bfloat16(Wg[idx]);
    }
}

// ===========================================================================
// bf16 tensor-core 64x64 GEMM + bias + relu
// ===========================================================================
__device__ __forceinline__ void gemm_tc(uint32_t sb, char* smc,
    uint32_t aoff, uint32_t woff, const float* __restrict__ biasS, uint32_t ooff,
    int lane, int w4, int h)
{
    const int bro = ((lane & 16) >> 1) + (lane & 7);
    const int bco = (lane & 8) * 2;
    uint32_t af[4][4];
    uint32_t abase = sb + aoff + (w4 * 16 + (lane & 15)) * 144 + ((lane >> 4) << 4);
#pragma unroll
    for (int ks = 0; ks < 4; ++ks) ldsm4(af[ks], abase + ks * 32);

    float C[4][4];
#pragma unroll
    for (int j = 0; j < 4; ++j)
#pragma unroll
        for (int e = 0; e < 4; ++e) C[j][e] = 0.f;

#pragma unroll
    for (int ks = 0; ks < 4; ++ks) {
#pragma unroll
        for (int p = 0; p < 2; ++p) {
            uint32_t wb[4];
            ldsm4(wb, sb + woff + (h * 32 + 16 * p + bro) * 144 + ks * 32 + bco);
            mma16816(C[2 * p],     af[ks], wb[0], wb[1]);
            mma16816(C[2 * p + 1], af[ks], wb[2], wb[3]);
        }
    }

    const int rl = w4 * 16 + (lane >> 2), rh = rl + 8;
#pragma unroll
    for (int j = 0; j < 4; ++j) {
        int n = h * 32 + 8 * j + (lane & 3) * 2;
        float b0 = biasS[n], b1 = biasS[n + 1];
        uint32_t u0 = pack_bf16x2(fmaxf(C[j][0] + b0, 0.f), fmaxf(C[j][1] + b1, 0.f));
        uint32_t u1 = pack_bf16x2(fmaxf(C[j][2] + b0, 0.f), fmaxf(C[j][3] + b1, 0.f));
        *(uint32_t*)(smc + ooff + rl * 144 + n * 2) = u0;
        *(uint32_t*)(smc + ooff + rh * 144 + n * 2) = u1;
    }
}

// ===========================================================================
// Merged projection kernel (unchanged from R11)
// ===========================================================================
#define AOFF  0
#define BOFF  9216
#define S1OFF 17408
#define WTOFF 34816
#define W0OFF 51456
#define W1OFF 60672
#define W2OFF 69888
#define BS0   79104
#define BS1   79360
#define BS2   79616
#define P2_SMEM 79872

__global__ __launch_bounds__(256, 2)
void proj2_kernel(const float* __restrict__ x, const float* __restrict__ event,
                  const float* __restrict__ Wx0, const float* __restrict__ bx0,
                  const float* __restrict__ Wx1, const float* __restrict__ bx1,
                  const float* __restrict__ We0, const float* __restrict__ be0,
                  const float* __restrict__ We1, const float* __restrict__ be1,
                  const float* __restrict__ Wq,  const float* __restrict__ bq,
                  const float* __restrict__ Wk,  const float* __restrict__ bk,
                  const float* __restrict__ Wv,  const float* __restrict__ bv)
{
    extern __shared__ char smc[];
    const uint32_t sb = smem_u32(smc);
    const int tid = threadIdx.x;
    const int lane = tid & 31, w = tid >> 5;
    const int w4 = w & 3, h = w >> 2;
    const int path = blockIdx.x / 144;
    const int id   = blockIdx.x % 144;
    const int b = id / 36, n0 = (id % 36) * 64;

    float* bias0 = (float*)(smc + BS0);
    float* bias1 = (float*)(smc + BS1);
    float* bias2 = (float*)(smc + BS2);
    if (tid < 64) {
        bias0[tid] = path == 0 ? bx1[tid] : be0[tid];
        bias1[tid] = path == 0 ? bq[tid]  : be1[tid];
        bias2[tid] = path == 0 ? bv[tid]  : bk[tid];
    }
    if (path == 0 && tid == 0) g_flag[id] = 0;

    if (path == 0) {
        float* S0 = (float*)smc;
        float* S1 = (float*)(smc + S1OFF);
        float* Wt = (float*)(smc + WTOFF);
        const float* xb = x + b * 64 * NPOS + n0;
#pragma unroll
        for (int idx = tid; idx < 4096; idx += 256) {
            int c = idx >> 6, j = idx & 63;
            S0[c * SP + j] = xb[c * NPOS + j];
        }
        loadWt(Wx0, Wt, tid);
        convW(Wx1, smc, W0OFF, tid);
        convW(Wq,  smc, W1OFF, tid);
        convW(Wv,  smc, W2OFF, tid);
        __syncthreads();
        gemm64_relu(S0, Wt, bx0, S1, tid & 15, tid >> 4);
        __syncthreads();

        float* x1g = g_x1 + b * 64 * NPOS + n0;
#pragma unroll
        for (int idx = tid; idx < 4096; idx += 256) {
            int c = idx >> 6, j = idx & 63;
            x1g[c * NPOS + j] = S1[c * SP + j];
        }
#pragma unroll
        for (int idx = tid; idx < 4096; idx += 256) {
            int j = idx & 63, o = idx >> 6;
            *(__nv_bfloat16*)(smc + AOFF + j * 144 + o * 2) = __float2bfloat16(S1[o * SP + j]);
        }
        __syncthreads();

        gemm_tc(sb, smc, AOFF, W0OFF, bias0, BOFF, lane, w4, h);   // x2 -> B
        __syncthreads();
        gemm_tc(sb, smc, BOFF, W1OFF, bias1, AOFF, lane, w4, h);   // q -> A
        __syncthreads();
        {
            char* qg = (char*)(g_qb + (size_t)(b * NPOS + n0) * 64);
#pragma unroll
            for (int it = 0; it < 2; ++it) {
                int idx = tid + it * 256;
                int p = idx >> 3, c16 = (idx & 7) * 16;
                *(uint4*)(qg + p * 128 + c16) = *(const uint4*)(smc + AOFF + p * 144 + c16);
            }
        }
        __syncthreads();
        gemm_tc(sb, smc, BOFF, W2OFF, bias2, AOFF, lane, w4, h);   // v -> A
        __syncthreads();
        {
            char* vbg = (char*)(g_vb + (size_t)b * 64 * NPOS + n0);
#pragma unroll
            for (int idx = tid; idx < 2048; idx += 256) {
                int c = idx >> 5, p2 = (idx & 31) * 2;
                uint32_t lo = *(const uint16_t*)(smc + AOFF + p2 * 144 + c * 2);
                uint32_t hi = *(const uint16_t*)(smc + AOFF + (p2 + 1) * 144 + c * 2);
                *(uint32_t*)(vbg + (size_t)c * (NPOS * 2) + p2 * 2) = lo | (hi << 16);
            }
        }
    } else {
        const float* eb = event + (long)b * 64 * 768 * 768;
#pragma unroll
        for (int idx = tid; idx < 4096; idx += 256) {
            int j = idx & 63, c = idx >> 6;
            int n = n0 + j;
            int hh = n / 48;
            int ww = n - hh * 48;
            float v = eb[((long)c * 768 + hh * 16) * 768 + ww * 16];
            *(__nv_bfloat16*)(smc + AOFF + j * 144 + c * 2) = __float2bfloat16(v);
        }
        convW(We0, smc, W0OFF, tid);
        convW(We1, smc, W1OFF, tid);
        convW(Wk,  smc, W2OFF, tid);
        __syncthreads();
        gemm_tc(sb, smc, AOFF, W0OFF, bias0, BOFF, lane, w4, h);   // ef0 -> B
        __syncthreads();
        gemm_tc(sb, smc, BOFF, W1OFF, bias1, AOFF, lane, w4, h);   // ef1 -> A
        __syncthreads();
        gemm_tc(sb, smc, AOFF, W2OFF, bias2, BOFF, lane, w4, h);   // k -> B
        __syncthreads();
        {
            char* kgd = (char*)(g_kb + (size_t)(b * NPOS + n0) * 64);
#pragma unroll
            for (int it = 0; it < 2; ++it) {
                int idx = tid + it * 256;
                int p = idx >> 3, c16 = (idx & 7) * 16;
                *(uint4*)(kgd + p * 128 + c16) = *(const uint4*)(smc + BOFF + p * 144 + c16);
            }
        }
    }
}

// ===========================================================================
// mma.sync attention (R11 structure), mainloop unrolled x3 so the 3-stage
// ring indices are compile-time constants (immediate smem addressing).
// ===========================================================================
#define TSTRIDE 144
#define SM_Q   0
#define SM_K   9216
#define SM_V   36864
#define SM_O   9216
#define SM_L   26624
#define ATTN_SMEM 64512
#define KITERS 18

__global__ __launch_bounds__(256, 2)
void attn_mma_kernel(const float* __restrict__ gamma, float* __restrict__ out)
{
    extern __shared__ char smc[];
    const uint32_t sb = smem_u32(smc);
    const int tid = threadIdx.x;
    const int lane = tid & 31, w = tid >> 5;
    const int w4 = w & 3, h = w >> 2;
    const int pairid = blockIdx.x >> 1;
    const int b   = blockIdx.x / 72;
    const int rem = blockIdx.x % 72;
    const int m0  = (rem >> 1) * 64;
    const int kh  = rem & 1;
    const int nbase = kh * 1152;

    const char* qg = (const char*)(g_qb + (size_t)(b * NPOS + m0) * 64);
    const char* kg = (const char*)(g_kb + (size_t)(b * NPOS + nbase) * 64);
    const char* vg = (const char*)(g_vb + (size_t)b * 64 * NPOS) + nbase * 2;

    const int row0 = tid >> 3,         c16_0 = (tid & 7) * 16;
    const int row1 = (tid + 256) >> 3, c16_1 = (tid & 7) * 16;

    // hoisted per-thread pointers/addresses for the copy loops
    const char* kg_r0 = kg + row0 * 128 + c16_0;
    const char* kg_r1 = kg + row1 * 128 + c16_1;
    const char* vg_r0 = vg + (size_t)row0 * (NPOS * 2) + c16_0;
    const char* vg_r1 = vg + (size_t)row1 * (NPOS * 2) + c16_1;
    const uint32_t sk_r0 = sb + SM_K + row0 * TSTRIDE + c16_0;
    const uint32_t sk_r1 = sb + SM_K + row1 * TSTRIDE + c16_1;
    const uint32_t sv_r0 = sb + SM_V + row0 * TSTRIDE + c16_0;
    const uint32_t sv_r1 = sb + SM_V + row1 * TSTRIDE + c16_1;

    CP16(sb + SM_Q + row0 * TSTRIDE + c16_0, qg + row0 * 128 + c16_0);
    CP16(sb + SM_Q + row1 * TSTRIDE + c16_1, qg + row1 * 128 + c16_1);
    CP16(sk_r0, kg_r0);
    CP16(sk_r1, kg_r1);
    CP16(sv_r0, vg_r0);
    CP16(sv_r1, vg_r1);
    CP_COMMIT();
    CP16(sk_r0 + 9216, kg_r0 + 64 * 128);
    CP16(sk_r1 + 9216, kg_r1 + 64 * 128);
    CP16(sv_r0 + 9216, vg_r0 + 128);
    CP16(sv_r1 + 9216, vg_r1 + 128);
    CP_COMMIT();
    CP_WAIT1();
    __syncthreads();

    uint32_t qf[4][4];
    {
        uint32_t base = sb + SM_Q + (w4 * 16 + (lane & 15)) * TSTRIDE + ((lane >> 4) << 4);
#pragma unroll
        for (int ks = 0; ks < 4; ++ks) ldsm4(qf[ks], base + ks * 32);
    }

    float O[8][4];
#pragma unroll
    for (int j = 0; j < 8; ++j)
#pragma unroll
        for (int e = 0; e < 4; ++e) O[j][e] = 0.f;
    float lsum0 = 0.f, lsum1 = 0.f;

    const int bro = ((lane & 16) >> 1) + (lane & 7);
    const int bco = (lane & 8) * 2;
    // hoisted ldsm bases (stage offset added as compile-time constant)
    const uint32_t kql = sb + SM_K + (h * 32 + bro) * TSTRIDE + bco;   // + 16p*144 + ks*32
    const uint32_t vql = sb + SM_V + bro * TSTRIDE + h * 64 + bco;     // + 16p*144 + step*32

    for (int ibase = 0; ibase < KITERS; ibase += 3) {
#pragma unroll
        for (int ii = 0; ii < 3; ++ii) {
            const int i = ibase + ii;
            const uint32_t CUR = (uint32_t)ii * 9216;            // compile-time per ii
            const uint32_t NX2 = (uint32_t)((ii + 2) % 3) * 9216;

            if (i + 2 < KITERS) {
                const int n2 = (i + 2) * 64;
                CP16(sk_r0 + NX2, kg_r0 + (size_t)n2 * 128);
                CP16(sk_r1 + NX2, kg_r1 + (size_t)n2 * 128);
                CP16(sv_r0 + NX2, vg_r0 + n2 * 2);
                CP16(sv_r1 + NX2, vg_r1 + n2 * 2);
            }
            CP_COMMIT();

            float S[4][4];
#pragma unroll
            for (int j = 0; j < 4; ++j)
#pragma unroll
                for (int e = 0; e < 4; ++e) S[j][e] = 0.f;
#pragma unroll
            for (int ks = 0; ks < 4; ++ks) {
#pragma unroll
                for (int p = 0; p < 2; ++p) {
                    uint32_t kb[4];
                    ldsm4(kb, kql + CUR + 16 * p * TSTRIDE + ks * 32);
                    mma16816(S[2 * p],     qf[ks], kb[0], kb[1]);
                    mma16816(S[2 * p + 1], qf[ks], kb[2], kb[3]);
                }
            }

            uint32_t P[2][4];
#pragma unroll
            for (int j = 0; j < 4; ++j) {
                float e0 = __expf(S[j][0] - EXP_SHIFT);
                float e1 = __expf(S[j][1] - EXP_SHIFT);
                float e2 = __expf(S[j][2] - EXP_SHIFT);
                float e3 = __expf(S[j][3] - EXP_SHIFT);
                lsum0 += e0 + e1;
                lsum1 += e2 + e3;
                P[j >> 1][(j & 1) * 2 + 0] = pack_bf16x2(e0, e1);
                P[j >> 1][(j & 1) * 2 + 1] = pack_bf16x2(e2, e3);
            }

#pragma unroll
            for (int step = 0; step < 2; ++step) {
#pragma unroll
                for (int p = 0; p < 4; ++p) {
                    uint32_t vb[4];
                    ldsm4(vb, vql + CUR + 16 * p * TSTRIDE + step * 32);
                    mma16816(O[2 * p],     P[step], vb[0], vb[1]);
                    mma16816(O[2 * p + 1], P[step], vb[2], vb[3]);
                }
            }

            CP_WAIT1();
            __syncthreads();
        }
    }

    lsum0 += __shfl_xor_sync(0xffffffffu, lsum0, 1);
    lsum0 += __shfl_xor_sync(0xffffffffu, lsum0, 2);
    lsum1 += __shfl_xor_sync(0xffffffffu, lsum1, 1);
    lsum1 += __shfl_xor_sync(0xffffffffu, lsum1, 2);

    float* so  = (float*)(smc + SM_O);
    float* lar = (float*)(smc + SM_L);
    const int g = lane >> 2, t2 = (lane & 3) * 2;
    const int m_lo = w4 * 16 + g, m_hi = m_lo + 8;

    if (h == 0) {
#pragma unroll
        for (int j = 0; j < 8; ++j) {
            int c = 8 * j + t2;
            so[c * 68 + m_lo]       = O[j][0];
            so[(c + 1) * 68 + m_lo] = O[j][1];
            so[c * 68 + m_hi]       = O[j][2];
            so[(c + 1) * 68 + m_hi] = O[j][3];
        }
        if ((lane & 3) == 0) { lar[m_lo] = lsum0; lar[m_hi] = lsum1; }
    }
    __syncthreads();
    if (h == 1) {
#pragma unroll
        for (int j = 0; j < 8; ++j) {
            int c = 8 * j + t2;
            so[c * 68 + m_lo]       += O[j][0];
            so[(c + 1) * 68 + m_lo] += O[j][1];
            so[c * 68 + m_hi]       += O[j][2];
            so[(c + 1) * 68 + m_hi] += O[j][3];
        }
        if ((lane & 3) == 0) { lar[m_lo] += lsum0; lar[m_hi] += lsum1; }
    }
    __syncthreads();

    float* pb = g_part + (size_t)blockIdx.x * 4096;
#pragma unroll
    for (int it = 0; it < 4; ++it) {
        int idx = tid + it * 256;
        int c = idx >> 4, m4 = (idx & 15) * 4;
        *(float4*)(pb + c * 64 + m4) = *(const float4*)(so + c * 68 + m4);
    }
    if (tid < 64) g_lpart[blockIdx.x * 64 + tid] = lar[tid];

    __threadfence();
    __shared__ int isLast;
    if (tid == 0) isLast = (atomicAdd(&g_flag[pairid], 1) == 1);
    __syncthreads();
    if (!isLast) return;

    const int peer = blockIdx.x ^ 1;
    const float gm = THITA * gamma[0];
    if (tid < 64) lar[tid] = gm / (lar[tid] + g_lpart[peer * 64 + tid]);
    __syncthreads();

    const float* pp  = g_part + (size_t)peer * 4096;
    const float* x1b = g_x1 + (size_t)b * 64 * NPOS + m0;
    float* ob = out + (size_t)b * 64 * NPOS + m0;
#pragma unroll
    for (int it = 0; it < 4; ++it) {
        int idx = tid + it * 256;
        int c = idx >> 4, m4 = (idx & 15) * 4;
        float4 a4 = *(const float4*)(so + c * 68 + m4);
        float4 b4 = *(const float4*)(pp + c * 64 + m4);
        float4 l4 = *(const float4*)(lar + m4);
        float4 xv = *(const float4*)(x1b + (size_t)c * NPOS + m4);
        float4 r;
        r.x = (a4.x + b4.x) * l4.x + xv.x;
        r.y = (a4.y + b4.y) * l4.y + xv.y;
        r.z = (a4.z + b4.z) * l4.z + xv.z;
        r.w = (a4.w + b4.w) * l4.w + xv.w;
        *(float4*)(ob + (size_t)c * NPOS + m4) = r;
    }
}

// ===========================================================================
extern "C" void kernel_launch(void* const* d_in, const int* in_sizes, int n_in,
                              void* d_out, int out_size)
{
    const float* x     = (const float*)d_in[0];
    const float* event = (const float*)d_in[1];
    const float* Wx0 = (const float*)d_in[2];
    const float* bx0 = (const float*)d_in[3];
    const float* Wx1 = (const float*)d_in[4];
    const float* bx1 = (const float*)d_in[5];
    const float* We0 = (const float*)d_in[6];
    const float* be0 = (const float*)d_in[7];
    const float* We1 = (const float*)d_in[8];
    const float* be1 = (const float*)d_in[9];
    const float* Wq  = (const float*)d_in[10];
    const float* bq  = (const float*)d_in[11];
    const float* Wk  = (const float*)d_in[12];
    const float* bk  = (const float*)d_in[13];
    const float* Wv  = (const float*)d_in[14];
    const float* bv  = (const float*)d_in[15];
    const float* gamma = (const float*)d_in[16];
    float* out = (float*)d_out;

    cudaFuncSetAttribute(proj2_kernel, cudaFuncAttributeMaxDynamicSharedMemorySize, P2_SMEM);
    cudaFuncSetAttribute(attn_mma_kernel, cudaFuncAttributeMaxDynamicSharedMemorySize, ATTN_SMEM);

    proj2_kernel<<<288, 256, P2_SMEM>>>(x, event,
                                        Wx0, bx0, Wx1, bx1,
                                        We0, be0, We1, be1,
                                        Wq, bq, Wk, bk, Wv, bv);
    attn_mma_kernel<<<288, 256, ATTN_SMEM>>>(gamma, out);
}